// round 4
// baseline (speedup 1.0000x reference)
#include <cuda_runtime.h>

// Ordered_GCN: B=64, N=207, K=32, C=8, D_IN=64, D_OUT=64, tokens = 13248.
// R4: warp-local per-token path (no block barriers inside a chunk), W rows
// register-resident (32 x f32x2 per thread), GEMV mean reads via LDS.128,
// and TWO tokens processed jointly per inner step for ILP.

#define KNB   32
#define DIN   64
#define NTHR  512
#define CHUNK 8
#define TOKEN_IN  2048   // floats per token (32*64)
#define TOKEN_OUT 512    // floats per token (8*64)

#define WIN_FLOATS (2 * CHUNK * TOKEN_IN)   // 128KB
#define IDX_INTS   (2 * CHUNK * KNB)        // 2KB
#define MEAN_U64S  (16 * 64)                // 16 warps x 2 slots x 32 pairs = 8KB
#define SMEM_BYTES (WIN_FLOATS * 4 + IDX_INTS * 4 + MEAN_U64S * 8)

typedef unsigned long long u64;

__device__ __forceinline__ u64 ffma2(u64 a, u64 b, u64 c) {
    u64 d;
    asm("fma.rn.f32x2 %0, %1, %2, %3;" : "=l"(d) : "l"(a), "l"(b), "l"(c));
    return d;
}
__device__ __forceinline__ u64 pack_f2(float x, float y) {
    u64 r; asm("mov.b64 %0, {%1, %2};" : "=l"(r) : "f"(x), "f"(y)); return r;
}
__device__ __forceinline__ void unpack_f2(u64 v, float& x, float& y) {
    asm("mov.b64 {%0, %1}, %2;" : "=f"(x), "=f"(y) : "l"(v));
}
__device__ __forceinline__ void cp_async16(void* smem, const void* gmem) {
    unsigned saddr = (unsigned)__cvta_generic_to_shared(smem);
    asm volatile("cp.async.cg.shared.global [%0], [%1], 16;" :: "r"(saddr), "l"(gmem));
}

__device__ __forceinline__ float fast_tanh(float z) {
    // 1 - 2/(e^{2z}+1): ~1e-7 abs err, correct saturation
    float e = __expf(2.0f * z);
    return 1.0f - __fdividef(2.0f, e + 1.0f);
}

__global__ void __launch_bounds__(NTHR, 1)
ordered_gcn_kernel(const int* __restrict__ idx,
                   const float* __restrict__ win,
                   const float* __restrict__ W,
                   float* __restrict__ out,
                   int total, int ngroups)
{
    extern __shared__ float smem[];
    float* win_s = smem;                               // [2][CHUNK][2048]
    int*   idx_s = (int*)(smem + WIN_FLOATS);          // [2][CHUNK][32]
    u64*   mean2 = (u64*)(idx_s + IDX_INTS);           // [16 warps][2][32]

    const int tid  = threadIdx.x;
    const int lane = tid & 31;
    const int warp = tid >> 5;
    const int c    = warp >> 1;                 // class (warp-uniform)
    const int o    = ((warp & 1) << 5) | lane;  // output column 0..63

    // ---- W[c][o][0:64] register-resident as 32 packed f32x2 ----
    u64 w[32];
    {
        const float4* gw = (const float4*)(W + ((c * DIN + o) * DIN));
        #pragma unroll
        for (int j = 0; j < 16; j++) {
            float4 v = gw[j];
            w[2*j]   = pack_f2(v.x, v.y);
            w[2*j+1] = pack_f2(v.z, v.w);
        }
    }

    const int grid = gridDim.x;
    const int bid  = blockIdx.x;

    auto issue_group = [&](int g, int b) {
        if (g < ngroups) {
            int base = g * CHUNK;
            float* wdst = win_s + b * (CHUNK * TOKEN_IN);
            #pragma unroll
            for (int j = 0; j < CHUNK; j++) {
                int tok = base + j;
                if (tok < total)
                    cp_async16(wdst + j * TOKEN_IN + tid * 4,
                               win + (size_t)tok * TOKEN_IN + tid * 4);
            }
            if (tid < 64) {
                int j = tid >> 3, sl = (tid & 7) * 4;
                int tok = base + j;
                if (tok < total)
                    cp_async16(idx_s + b * (CHUNK * KNB) + j * KNB + sl,
                               idx + (size_t)tok * KNB + sl);
            }
        }
        asm volatile("cp.async.commit_group;");
    };

    issue_group(bid, 0);
    issue_group(bid + grid, 1);

    int it = 0;
    for (int g = bid; g < ngroups; g += grid, ++it) {
        asm volatile("cp.async.wait_group 1;");
        __syncthreads();

        const int buf  = it & 1;
        const int base = g * CHUNK;
        const float* wbuf = win_s + buf * (CHUNK * TOKEN_IN);
        const int*   ibuf = idx_s + buf * (CHUNK * KNB);
        u64* slotA = mean2 + warp * 64;
        u64* slotB = slotA + 32;

        #pragma unroll
        for (int j = 0; j < CHUNK; j += 2) {
            const int tokA = base + j;
            const int tokB = base + j + 1;
            if (tokA >= total) break;
            const bool haveB = (tokB < total);
            const int jB = haveB ? (j + 1) : j;   // clamp: compute garbage, guard store

            // ---- membership masks (class c warp-uniform) ----
            const int myA = ibuf[j  * KNB + lane];
            const int myB = ibuf[jB * KNB + lane];
            unsigned maskA = __ballot_sync(0xffffffffu, myA == c);
            unsigned maskB = __ballot_sync(0xffffffffu, myB == c);
            const int cntA = __popc(maskA), cntB = __popc(maskB);
            const float rcA = __fdividef(1.0f, (float)(cntA > 0 ? cntA : 1));
            const float rcB = __fdividef(1.0f, (float)(cntB > 0 ? cntB : 1));

            // ---- class sums for d = 2*lane, 2*lane+1 (two independent loops) ----
            float a0 = 0.0f, a1 = 0.0f, b0 = 0.0f, b1 = 0.0f;
            {
                const float2* rowA = (const float2*)(wbuf + j  * TOKEN_IN);
                const float2* rowB = (const float2*)(wbuf + jB * TOKEN_IN);
                unsigned mA = maskA, mB = maskB;
                while (mA | mB) {
                    if (mA) {
                        int k = __ffs(mA) - 1; mA &= mA - 1;
                        float2 v = rowA[k * 32 + lane];
                        a0 += v.x; a1 += v.y;
                    }
                    if (mB) {
                        int k = __ffs(mB) - 1; mB &= mB - 1;
                        float2 v = rowB[k * 32 + lane];
                        b0 += v.x; b1 += v.y;
                    }
                }
            }

            __syncwarp();                 // prior GEMV reads of slots done
            slotA[lane] = pack_f2(a0, a1);
            slotB[lane] = pack_f2(b0, b1);
            __syncwarp();                 // all pairs staged

            // ---- dual GEMV: 32 LDS.128 + 64 FFMA2, 4 acc chains ----
            const ulonglong2* mA2 = (const ulonglong2*)slotA;
            const ulonglong2* mB2 = (const ulonglong2*)slotB;
            u64 accA0 = 0ULL, accA1 = 0ULL, accB0 = 0ULL, accB1 = 0ULL;
            #pragma unroll
            for (int jj = 0; jj < 16; jj++) {
                ulonglong2 va = mA2[jj];
                ulonglong2 vb = mB2[jj];
                accA0 = ffma2(va.x, w[2*jj],     accA0);
                accA1 = ffma2(va.y, w[2*jj + 1], accA1);
                accB0 = ffma2(vb.x, w[2*jj],     accB0);
                accB1 = ffma2(vb.y, w[2*jj + 1], accB1);
            }
            float xa0, ya0, xa1, ya1, xb0, yb0, xb1, yb1;
            unpack_f2(accA0, xa0, ya0); unpack_f2(accA1, xa1, ya1);
            unpack_f2(accB0, xb0, yb0); unpack_f2(accB1, xb1, yb1);
            float zA = ((xa0 + xa1) + (ya0 + ya1)) * rcA;
            float zB = ((xb0 + xb1) + (yb0 + yb1)) * rcB;

            out[(size_t)tokA * TOKEN_OUT + (c << 6) + o] = fast_tanh(zA);
            if (haveB)
                out[(size_t)tokB * TOKEN_OUT + (c << 6) + o] = fast_tanh(zB);
        }

        __syncthreads();                  // all warps done with buf
        issue_group(g + 2 * grid, buf);   // refill consumed buffer
    }
}

extern "C" void kernel_launch(void* const* d_in, const int* in_sizes, int n_in,
                              void* d_out, int out_size) {
    const int*   idx = (const int*)d_in[0];   // [B,N,K] int32
    const float* win = (const float*)d_in[1]; // [B,N,K,D_IN] f32
    const float* W   = (const float*)d_in[2]; // [C,D_OUT,D_IN] f32
    float* out = (float*)d_out;               // [B,N,C,D_OUT] f32

    const int total   = in_sizes[0] / KNB;
    const int ngroups = (total + CHUNK - 1) / CHUNK;

    static int smem_set = 0;
    if (!smem_set) {
        cudaFuncSetAttribute(ordered_gcn_kernel,
                             cudaFuncAttributeMaxDynamicSharedMemorySize,
                             SMEM_BYTES);
        smem_set = 1;
    }

    int sms = 148, dev = 0;
    cudaGetDevice(&dev);
    cudaDeviceGetAttribute(&sms, cudaDevAttrMultiProcessorCount, dev);
    int grid = (sms < ngroups) ? sms : ngroups;

    ordered_gcn_kernel<<<grid, NTHR, SMEM_BYTES>>>(idx, win, W, out, total, ngroups);
}